// round 8
// baseline (speedup 1.0000x reference)
#include <cuda_runtime.h>
#include <math.h>

#define NCLS 6
#define TT 60
#define NBLK 192   // 3 scales * 64 batches, one (scale,batch) per block

// 12 global accumulators: [scale][k], k = {cls, iou, inner, npos}
__device__ float g_acc[12];
__device__ unsigned int g_count = 0;   // arrival counter; finisher resets to 0

__device__ __forceinline__ float bce_f(float x, float t) {
    return fmaxf(x, 0.0f) - x * t + __logf(1.0f + __expf(-fabsf(x)));
}

__device__ __forceinline__ float iou_f(float px, float py, float pw, float ph,
                                       float tx, float ty, float tw, float th) {
    float x11 = px - pw * 0.5f, y11 = py - ph * 0.5f;
    float x12 = px + pw * 0.5f, y12 = py + ph * 0.5f;
    float x21 = tx - tw * 0.5f, y21 = ty - th * 0.5f;
    float x22 = tx + tw * 0.5f, y22 = ty + th * 0.5f;
    float iw = fmaxf(fminf(x12, x22) - fmaxf(x11, x21), 0.0f);
    float ih = fmaxf(fminf(y12, y22) - fmaxf(y11, y21), 0.0f);
    float inter = iw * ih;
    float a1 = (x12 - x11) * (y12 - y11);
    float a2 = (x22 - x21) * (y22 - y21);
    return inter / (a1 + a2 - inter + 1e-7f);
}

__global__ void __launch_bounds__(64)
det_loss_main(const float* __restrict__ p3,
              const float* __restrict__ p4,
              const float* __restrict__ p5,
              const int*   __restrict__ tcls,
              const float* __restrict__ tbox) {
    const int bx = blockIdx.x;
    const int scale = bx >> 6;        // 0,1,2
    const int b = bx & 63;
    const int W = 160 >> scale;
    const float* __restrict__ pred = (scale == 0) ? p3 : ((scale == 1) ? p4 : p5);

    __shared__ int scell[TT];
    __shared__ unsigned char sclsid[TT];

    const int t = threadIdx.x;

    float txv = 0.f, tyv = 0.f, twv = 0.f, thv = 0.f;
    if (t < TT) {
        const float4 tb = ((const float4*)tbox)[(size_t)b * TT + t];
        txv = tb.x; tyv = tb.y; twv = tb.z; thv = tb.w;
        int gx = (int)(txv * (float)W);  gx = min(max(gx, 0), W - 1);
        int gy = (int)(tyv * (float)W);  gy = min(max(gy, 0), W - 1);
        scell[t]  = gy * W + gx;
        sclsid[t] = (unsigned char)tcls[b * TT + t];
    }
    __syncthreads();

    float cls_sum = 0.0f, iou_sum = 0.0f, inner_sum = 0.0f, npos = 0.0f;

    if (t < TT) {
        const int mycell = scell[t];

        // speculative gather — overlap the 10 scattered DRAM loads with the scan
        const int gy0 = mycell / W;
        const int gx0 = mycell - gy0 * W;
        const size_t HW  = (size_t)W * (size_t)W;
        const size_t off = (size_t)(b * 11) * HW + (size_t)gy0 * W + gx0;
        float cpred[NCLS];
        #pragma unroll
        for (int c = 0; c < NCLS; c++) cpred[c] = pred[off + (size_t)c * HW];
        const float px = pred[off + (size_t)7  * HW];
        const float py = pred[off + (size_t)8  * HW];
        const float pw = pred[off + (size_t)9  * HW];
        const float ph = pred[off + (size_t)10 * HW];

        // collision scan: last (highest index) target wins; cls mask ORs co-located
        unsigned mask = 0u;
        bool winner = true;
        #pragma unroll
        for (int j = 0; j < TT; j++) {
            if (scell[j] == mycell) {
                mask |= 1u << sclsid[j];
                if (j > t) winner = false;
            }
        }

        if (winner) {
            #pragma unroll
            for (int c = 0; c < NCLS; c++) {
                const float tv = ((mask >> c) & 1u) ? 1.0f : 0.0f;
                cls_sum += bce_f(cpred[c], tv);
            }
            const float iou   = iou_f(px, py, pw, ph, txv, tyv, twv, thv);
            const float inner = iou_f(px, py, pw * 0.7f, ph * 0.7f,
                                      txv, tyv, twv * 0.7f, thv * 0.7f);
            iou_sum   = 1.0f - iou;
            inner_sum = 1.0f - inner;
            npos      = 1.0f;
        }
    }

    // block reduce over 64 threads (2 warps) — all lanes participate
    const unsigned fullm = 0xFFFFFFFFu;
    #pragma unroll
    for (int s = 16; s > 0; s >>= 1) {
        cls_sum   += __shfl_down_sync(fullm, cls_sum,   s);
        iou_sum   += __shfl_down_sync(fullm, iou_sum,   s);
        inner_sum += __shfl_down_sync(fullm, inner_sum, s);
        npos      += __shfl_down_sync(fullm, npos,      s);
    }
    __shared__ float red[2][4];
    const int wid = t >> 5, lid = t & 31;
    if (lid == 0) {
        red[wid][0] = cls_sum; red[wid][1] = iou_sum;
        red[wid][2] = inner_sum; red[wid][3] = npos;
    }
    __syncthreads();

    // t0 alone publishes: 4 value atomics, release fence, arrival bump. No tail.
    if (t == 0) {
        const int base = scale * 4;
        atomicAdd(&g_acc[base + 0], red[0][0] + red[1][0]);
        atomicAdd(&g_acc[base + 1], red[0][1] + red[1][1]);
        atomicAdd(&g_acc[base + 2], red[0][2] + red[1][2]);
        atomicAdd(&g_acc[base + 3], red[0][3] + red[1][3]);
        __threadfence();
        atomicAdd(&g_count, 1u);
    }
}

__global__ void __launch_bounds__(32)
det_loss_fin(float* __restrict__ out) {
    if (threadIdx.x != 0) return;

    // spin until all NBLK blocks have arrived (bounded so ncu isolated-replay
    // of this kernel alone cannot hang the container)
    unsigned iters = 0;
    while (atomicAdd(&g_count, 0u) < (unsigned)NBLK) {
        if (++iters > 2000000u) return;   // pathological only; never in real runs
    }
    __threadfence();   // acquire: value atomics visible

    float sums[12];
    #pragma unroll
    for (int i = 0; i < 12; i++) sums[i] = __ldcg(&g_acc[i]);

    float cls_total = 0.0f, box_total = 0.0f;
    #pragma unroll
    for (int s2 = 0; s2 < 3; s2++) {
        const float np        = sums[s2 * 4 + 3];
        const float denom     = np + 1e-8f;
        const float cls_loss  = sums[s2 * 4 + 0] / denom;
        const float iou_term  = sums[s2 * 4 + 1] / denom;
        const float inner_t   = sums[s2 * 4 + 2] / denom;
        const float inner_iou = 0.5f * iou_term + 0.5f * inner_t;  // (1-INNER_W), INNER_W
        const float box_loss  = 0.5f * iou_term + 0.5f * inner_iou;
        cls_total += cls_loss;
        box_total += box_loss;
    }
    cls_total = cls_total / 3.0f;
    box_total = box_total / 3.0f;
    const float total = 0.5f * cls_total + 7.5f * box_total;
    out[0] = total;
    out[1] = cls_total;
    out[2] = box_total;

    // reset for next graph replay (ordered before next replay by graph boundary)
    #pragma unroll
    for (int i = 0; i < 12; i++) atomicExch(&g_acc[i], 0.0f);
    __threadfence();
    atomicExch(&g_count, 0u);
}

extern "C" void kernel_launch(void* const* d_in, const int* in_sizes, int n_in,
                              void* d_out, int out_size) {
    const float* p3   = (const float*)d_in[0];
    const float* p4   = (const float*)d_in[1];
    const float* p5   = (const float*)d_in[2];
    const int*   tcls = (const int*)  d_in[3];
    const float* tbox = (const float*)d_in[4];
    float* out = (float*)d_out;

    // Fork-join: finisher runs on a parallel branch and spin-waits; its launch
    // overhead + spin overlap the main kernel. Stream/events created once on
    // the first (non-captured correctness) call; captured work is identical
    // on every call.
    static cudaStream_t s2 = 0;
    static cudaEvent_t evFork = 0, evJoin = 0;
    if (s2 == 0) {
        cudaStreamCreateWithFlags(&s2, cudaStreamNonBlocking);
        cudaEventCreateWithFlags(&evFork, cudaEventDisableTiming);
        cudaEventCreateWithFlags(&evJoin, cudaEventDisableTiming);
    }

    cudaEventRecord(evFork, 0);                  // fork from capturing stream
    cudaStreamWaitEvent(s2, evFork, 0);
    det_loss_fin<<<1, 32, 0, s2>>>(out);         // concurrent spin-wait finisher
    cudaEventRecord(evJoin, s2);

    det_loss_main<<<NBLK, 64>>>(p3, p4, p5, tcls, tbox);

    cudaStreamWaitEvent(0, evJoin, 0);           // join: graph ends after finisher
}

// round 9
// speedup vs baseline: 1.1161x; 1.1161x over previous
#include <cuda_runtime.h>
#include <math.h>

#define NCLS 6
#define TT 60
#define NBLK 192   // 3 scales * 64 batches, one (scale,batch) per block

// 12 global accumulators: [scale][k], k = {cls, iou, inner, npos}
__device__ float g_acc[12];
__device__ unsigned int g_count = 0;   // arrival counter; last block resets to 0

__device__ __forceinline__ float bce_f(float x, float t) {
    return fmaxf(x, 0.0f) - x * t + __logf(1.0f + __expf(-fabsf(x)));
}

__device__ __forceinline__ float iou_f(float px, float py, float pw, float ph,
                                       float tx, float ty, float tw, float th) {
    float x11 = px - pw * 0.5f, y11 = py - ph * 0.5f;
    float x12 = px + pw * 0.5f, y12 = py + ph * 0.5f;
    float x21 = tx - tw * 0.5f, y21 = ty - th * 0.5f;
    float x22 = tx + tw * 0.5f, y22 = ty + th * 0.5f;
    float iw = fmaxf(fminf(x12, x22) - fmaxf(x11, x21), 0.0f);
    float ih = fmaxf(fminf(y12, y22) - fmaxf(y11, y21), 0.0f);
    float inter = iw * ih;
    float a1 = (x12 - x11) * (y12 - y11);
    float a2 = (x22 - x21) * (y22 - y21);
    return inter / (a1 + a2 - inter + 1e-7f);
}

__global__ void __launch_bounds__(64)
det_loss_fused(const float* __restrict__ p3,
               const float* __restrict__ p4,
               const float* __restrict__ p5,
               const int*   __restrict__ tcls,
               const float* __restrict__ tbox,
               float* __restrict__ out) {
    const int bx = blockIdx.x;
    const int scale = bx >> 6;        // 0,1,2
    const int b = bx & 63;
    const int W = 160 >> scale;
    const float* __restrict__ pred = (scale == 0) ? p3 : ((scale == 1) ? p4 : p5);

    __shared__ int scell[TT];
    __shared__ unsigned char sclsid[TT];

    const int t = threadIdx.x;

    float txv = 0.f, tyv = 0.f, twv = 0.f, thv = 0.f;
    float cpred[NCLS];
    float px = 0.f, py = 0.f, pw = 0.f, ph = 0.f;
    int mycell = 0;

    if (t < TT) {
        // RTT #1: own target box (coalesced float4) + class id
        const float4 tb = ((const float4*)tbox)[(size_t)b * TT + t];
        txv = tb.x; tyv = tb.y; twv = tb.z; thv = tb.w;
        const int myclsid = tcls[b * TT + t];

        int gx = (int)(txv * (float)W);  gx = min(max(gx, 0), W - 1);
        int gy = (int)(tyv * (float)W);  gy = min(max(gy, 0), W - 1);
        mycell = gy * W + gx;

        // RTT #2 issued IMMEDIATELY — depends only on this thread's own cell.
        // Barrier + collision scan below run while these 10 loads are in flight.
        const size_t HW  = (size_t)W * (size_t)W;
        const size_t off = (size_t)(b * 11) * HW + (size_t)gy * W + gx;
        #pragma unroll
        for (int c = 0; c < NCLS; c++) cpred[c] = pred[off + (size_t)c * HW];
        px = pred[off + (size_t)7  * HW];
        py = pred[off + (size_t)8  * HW];
        pw = pred[off + (size_t)9  * HW];
        ph = pred[off + (size_t)10 * HW];

        scell[t]  = mycell;
        sclsid[t] = (unsigned char)myclsid;
    }
    __syncthreads();

    float cls_sum = 0.0f, iou_sum = 0.0f, inner_sum = 0.0f, npos = 0.0f;

    if (t < TT) {
        // collision scan: last (highest index) target wins; cls mask ORs co-located
        unsigned mask = 0u;
        bool winner = true;
        #pragma unroll
        for (int j = 0; j < TT; j++) {
            if (scell[j] == mycell) {
                mask |= 1u << sclsid[j];
                if (j > t) winner = false;
            }
        }

        if (winner) {
            #pragma unroll
            for (int c = 0; c < NCLS; c++) {
                const float tv = ((mask >> c) & 1u) ? 1.0f : 0.0f;
                cls_sum += bce_f(cpred[c], tv);
            }
            const float iou   = iou_f(px, py, pw, ph, txv, tyv, twv, thv);
            const float inner = iou_f(px, py, pw * 0.7f, ph * 0.7f,
                                      txv, tyv, twv * 0.7f, thv * 0.7f);
            iou_sum   = 1.0f - iou;
            inner_sum = 1.0f - inner;
            npos      = 1.0f;
        }
    }

    // block reduce over 64 threads (2 warps) — all lanes participate
    const unsigned fullm = 0xFFFFFFFFu;
    #pragma unroll
    for (int s = 16; s > 0; s >>= 1) {
        cls_sum   += __shfl_down_sync(fullm, cls_sum,   s);
        iou_sum   += __shfl_down_sync(fullm, iou_sum,   s);
        inner_sum += __shfl_down_sync(fullm, inner_sum, s);
        npos      += __shfl_down_sync(fullm, npos,      s);
    }
    __shared__ float red[2][4];
    __shared__ bool s_is_last;
    const int wid = t >> 5, lid = t & 31;
    if (lid == 0) {
        red[wid][0] = cls_sum; red[wid][1] = iou_sum;
        red[wid][2] = inner_sum; red[wid][3] = npos;
    }
    __syncthreads();

    // t0 alone publishes (single-thread ordering: atomics -> fence -> arrival)
    if (t == 0) {
        const int base = scale * 4;
        atomicAdd(&g_acc[base + 0], red[0][0] + red[1][0]);
        atomicAdd(&g_acc[base + 1], red[0][1] + red[1][1]);
        atomicAdd(&g_acc[base + 2], red[0][2] + red[1][2]);
        atomicAdd(&g_acc[base + 3], red[0][3] + red[1][3]);
        __threadfence();
        const unsigned prev = atomicAdd(&g_count, 1u);
        s_is_last = (prev == NBLK - 1u);
    }
    __syncthreads();

    if (!s_is_last) return;

    // ── last block, t0 only: fence, 12 batched L2 loads, finish, reset ──
    if (t == 0) {
        __threadfence();   // acquire: all published atomics visible
        float sums[12];
        #pragma unroll
        for (int i = 0; i < 12; i++) sums[i] = __ldcg(&g_acc[i]);

        float cls_total = 0.0f, box_total = 0.0f;
        #pragma unroll
        for (int s2 = 0; s2 < 3; s2++) {
            const float np        = sums[s2 * 4 + 3];
            const float denom     = np + 1e-8f;
            const float cls_loss  = sums[s2 * 4 + 0] / denom;
            const float iou_term  = sums[s2 * 4 + 1] / denom;
            const float inner_t   = sums[s2 * 4 + 2] / denom;
            const float inner_iou = 0.5f * iou_term + 0.5f * inner_t;  // (1-INNER_W), INNER_W
            const float box_loss  = 0.5f * iou_term + 0.5f * inner_iou;
            cls_total += cls_loss;
            box_total += box_loss;
        }
        cls_total = cls_total / 3.0f;
        box_total = box_total / 3.0f;
        const float total = 0.5f * cls_total + 7.5f * box_total;
        out[0] = total;
        out[1] = cls_total;
        out[2] = box_total;

        // reset for next graph replay (same thread -> ordered)
        #pragma unroll
        for (int i = 0; i < 12; i++) g_acc[i] = 0.0f;
        __threadfence();
        g_count = 0;
    }
}

extern "C" void kernel_launch(void* const* d_in, const int* in_sizes, int n_in,
                              void* d_out, int out_size) {
    const float* p3   = (const float*)d_in[0];
    const float* p4   = (const float*)d_in[1];
    const float* p5   = (const float*)d_in[2];
    const int*   tcls = (const int*)  d_in[3];
    const float* tbox = (const float*)d_in[4];
    float* out = (float*)d_out;

    det_loss_fused<<<NBLK, 64>>>(p3, p4, p5, tcls, tbox, out);
}

// round 10
// speedup vs baseline: 1.1487x; 1.0292x over previous
#include <cuda_runtime.h>
#include <math.h>

#define NCLS 6
#define TT 60
#define NBLK 192   // 3 scales * 64 batches, one (scale,batch) per block
#define NTHR 640   // 10 channel-groups x 64 targets

// 12 global accumulators: [scale][k], k = {cls, iou, inner, npos}
__device__ float g_acc[12];
__device__ unsigned int g_count = 0;   // arrival counter; last block resets to 0

__device__ __forceinline__ float bce_f(float x, float t) {
    return fmaxf(x, 0.0f) - x * t + __logf(1.0f + __expf(-fabsf(x)));
}

__device__ __forceinline__ float iou_f(float px, float py, float pw, float ph,
                                       float tx, float ty, float tw, float th) {
    float x11 = px - pw * 0.5f, y11 = py - ph * 0.5f;
    float x12 = px + pw * 0.5f, y12 = py + ph * 0.5f;
    float x21 = tx - tw * 0.5f, y21 = ty - th * 0.5f;
    float x22 = tx + tw * 0.5f, y22 = ty + th * 0.5f;
    float iw = fmaxf(fminf(x12, x22) - fmaxf(x11, x21), 0.0f);
    float ih = fmaxf(fminf(y12, y22) - fmaxf(y11, y21), 0.0f);
    float inter = iw * ih;
    float a1 = (x12 - x11) * (y12 - y11);
    float a2 = (x22 - x21) * (y22 - y21);
    return inter / (a1 + a2 - inter + 1e-7f);
}

__global__ void __launch_bounds__(NTHR)
det_loss_fused(const float* __restrict__ p3,
               const float* __restrict__ p4,
               const float* __restrict__ p5,
               const int*   __restrict__ tcls,
               const float* __restrict__ tbox,
               float* __restrict__ out) {
    const int bx = blockIdx.x;
    const int scale = bx >> 6;        // 0,1,2
    const int b = bx & 63;
    const int W = 160 >> scale;
    const float* __restrict__ pred = (scale == 0) ? p3 : ((scale == 1) ? p4 : p5);

    const int tid = threadIdx.x;
    const int t = tid & 63;           // target index (active t<60)
    const int c = tid >> 6;           // channel group 0..9
    const int chan = (c < NCLS) ? c : (c + 1);   // 0..5 cls, 7..10 box

    __shared__ int scell[64];
    __shared__ unsigned char sclsid[64];
    __shared__ float sval[10][64];    // [channel-group][target]

    // Every thread derives its own cell from its own tbox read (L2 broadcast
    // across the 10 groups) — NO barrier between tbox RTT and the gather.
    float txv = 0.f, tyv = 0.f, twv = 0.f, thv = 0.f;
    if (t < TT) {
        const float4 tb = ((const float4*)tbox)[(size_t)b * TT + t];
        txv = tb.x; tyv = tb.y; twv = tb.z; thv = tb.w;
        int gx = (int)(txv * (float)W);  gx = min(max(gx, 0), W - 1);
        int gy = (int)(tyv * (float)W);  gy = min(max(gy, 0), W - 1);
        const int cell = gy * W + gx;

        // ONE scattered load per thread — 10x the warps, 32-deep queues
        const size_t HW = (size_t)W * (size_t)W;
        sval[c][t] = pred[((size_t)(b * 11) + chan) * HW + cell];

        if (c == 0) {
            scell[t]  = cell;
            sclsid[t] = (unsigned char)tcls[b * TT + t];
        }
    }
    __syncthreads();

    float cls_sum = 0.0f, iou_sum = 0.0f, inner_sum = 0.0f, npos = 0.0f;

    // compute group: warps 0-1 (tid 0..63) — all 64 lanes resident
    if (tid < 64) {
        if (t < TT) {
            const int mycell = scell[t];
            // collision scan: last (highest index) target wins; OR class bits
            unsigned mask = 0u;
            bool winner = true;
            #pragma unroll
            for (int j = 0; j < TT; j++) {
                if (scell[j] == mycell) {
                    mask |= 1u << sclsid[j];
                    if (j > t) winner = false;
                }
            }
            if (winner) {
                #pragma unroll
                for (int cc = 0; cc < NCLS; cc++) {
                    const float tv = ((mask >> cc) & 1u) ? 1.0f : 0.0f;
                    cls_sum += bce_f(sval[cc][t], tv);
                }
                const float px = sval[6][t], py = sval[7][t];
                const float pw = sval[8][t], ph = sval[9][t];
                const float iou   = iou_f(px, py, pw, ph, txv, tyv, twv, thv);
                const float inner = iou_f(px, py, pw * 0.7f, ph * 0.7f,
                                          txv, tyv, twv * 0.7f, thv * 0.7f);
                iou_sum   = 1.0f - iou;
                inner_sum = 1.0f - inner;
                npos      = 1.0f;
            }
        }

        // reduce within warps 0-1 (full warps — no partial-warp shuffle)
        const unsigned fullm = 0xFFFFFFFFu;
        #pragma unroll
        for (int s = 16; s > 0; s >>= 1) {
            cls_sum   += __shfl_down_sync(fullm, cls_sum,   s);
            iou_sum   += __shfl_down_sync(fullm, iou_sum,   s);
            inner_sum += __shfl_down_sync(fullm, inner_sum, s);
            npos      += __shfl_down_sync(fullm, npos,      s);
        }
    }

    __shared__ float red[2][4];
    __shared__ bool s_is_last;
    if (tid < 64 && (tid & 31) == 0) {
        const int wid = tid >> 5;
        red[wid][0] = cls_sum; red[wid][1] = iou_sum;
        red[wid][2] = inner_sum; red[wid][3] = npos;
    }
    __syncthreads();

    // t0 alone publishes (single-thread ordering: atomics -> fence -> arrival)
    if (tid == 0) {
        const int base = scale * 4;
        atomicAdd(&g_acc[base + 0], red[0][0] + red[1][0]);
        atomicAdd(&g_acc[base + 1], red[0][1] + red[1][1]);
        atomicAdd(&g_acc[base + 2], red[0][2] + red[1][2]);
        atomicAdd(&g_acc[base + 3], red[0][3] + red[1][3]);
        __threadfence();
        const unsigned prev = atomicAdd(&g_count, 1u);
        s_is_last = (prev == NBLK - 1u);
    }
    __syncthreads();

    if (!s_is_last) return;

    // ── last block, t0 only: fence, 12 batched L2 loads, finish, reset ──
    if (tid == 0) {
        __threadfence();   // acquire: all published atomics visible
        float sums[12];
        #pragma unroll
        for (int i = 0; i < 12; i++) sums[i] = __ldcg(&g_acc[i]);

        float cls_total = 0.0f, box_total = 0.0f;
        #pragma unroll
        for (int s2 = 0; s2 < 3; s2++) {
            const float np        = sums[s2 * 4 + 3];
            const float denom     = np + 1e-8f;
            const float cls_loss  = sums[s2 * 4 + 0] / denom;
            const float iou_term  = sums[s2 * 4 + 1] / denom;
            const float inner_t   = sums[s2 * 4 + 2] / denom;
            const float inner_iou = 0.5f * iou_term + 0.5f * inner_t;  // (1-INNER_W), INNER_W
            const float box_loss  = 0.5f * iou_term + 0.5f * inner_iou;
            cls_total += cls_loss;
            box_total += box_loss;
        }
        cls_total = cls_total / 3.0f;
        box_total = box_total / 3.0f;
        const float total = 0.5f * cls_total + 7.5f * box_total;
        out[0] = total;
        out[1] = cls_total;
        out[2] = box_total;

        // reset for next graph replay (same thread -> ordered)
        #pragma unroll
        for (int i = 0; i < 12; i++) g_acc[i] = 0.0f;
        __threadfence();
        g_count = 0;
    }
}

extern "C" void kernel_launch(void* const* d_in, const int* in_sizes, int n_in,
                              void* d_out, int out_size) {
    const float* p3   = (const float*)d_in[0];
    const float* p4   = (const float*)d_in[1];
    const float* p5   = (const float*)d_in[2];
    const int*   tcls = (const int*)  d_in[3];
    const float* tbox = (const float*)d_in[4];
    float* out = (float*)d_out;

    det_loss_fused<<<NBLK, NTHR>>>(p3, p4, p5, tcls, tbox, out);
}

// round 11
// speedup vs baseline: 1.1761x; 1.0239x over previous
#include <cuda_runtime.h>
#include <math.h>

#define NCLS 6
#define TT 60
#define NBLK 192   // 3 scales * 64 batches, one (scale,batch) per block

// per-block partials, one float4 slot per block: {cls, iou, inner, npos}
__device__ float4 g_part[NBLK];
__device__ unsigned int g_count = 0;   // arrival counter; last block resets to 0

__device__ __forceinline__ float bce_f(float x, float t) {
    return fmaxf(x, 0.0f) - x * t + __logf(1.0f + __expf(-fabsf(x)));
}

__device__ __forceinline__ float iou_f(float px, float py, float pw, float ph,
                                       float tx, float ty, float tw, float th) {
    float x11 = px - pw * 0.5f, y11 = py - ph * 0.5f;
    float x12 = px + pw * 0.5f, y12 = py + ph * 0.5f;
    float x21 = tx - tw * 0.5f, y21 = ty - th * 0.5f;
    float x22 = tx + tw * 0.5f, y22 = ty + th * 0.5f;
    float iw = fmaxf(fminf(x12, x22) - fmaxf(x11, x21), 0.0f);
    float ih = fmaxf(fminf(y12, y22) - fmaxf(y11, y21), 0.0f);
    float inter = iw * ih;
    float a1 = (x12 - x11) * (y12 - y11);
    float a2 = (x22 - x21) * (y22 - y21);
    return inter / (a1 + a2 - inter + 1e-7f);
}

// acq_rel fetch-add on the arrival counter: release publishes this block's
// partial slot; acquire on the final arrival makes ALL slots visible.
__device__ __forceinline__ unsigned int arrive_acq_rel(unsigned int* p) {
    unsigned int old;
    asm volatile("atom.acq_rel.gpu.global.add.u32 %0, [%1], 1;"
                 : "=r"(old) : "l"(p) : "memory");
    return old;
}

__global__ void __launch_bounds__(64)
det_loss_fused(const float* __restrict__ p3,
               const float* __restrict__ p4,
               const float* __restrict__ p5,
               const int*   __restrict__ tcls,
               const float* __restrict__ tbox,
               float* __restrict__ out) {
    const int bx = blockIdx.x;
    const int scale = bx >> 6;        // 0,1,2
    const int b = bx & 63;
    const int W = 160 >> scale;
    const float* __restrict__ pred = (scale == 0) ? p3 : ((scale == 1) ? p4 : p5);

    __shared__ int scell[TT];
    __shared__ unsigned char sclsid[TT];

    const int t = threadIdx.x;

    // RTT #1: own target box (coalesced float4)
    float txv = 0.f, tyv = 0.f, twv = 0.f, thv = 0.f;
    if (t < TT) {
        const float4 tb = ((const float4*)tbox)[(size_t)b * TT + t];
        txv = tb.x; tyv = tb.y; twv = tb.z; thv = tb.w;
        int gx = (int)(txv * (float)W);  gx = min(max(gx, 0), W - 1);
        int gy = (int)(tyv * (float)W);  gy = min(max(gy, 0), W - 1);
        scell[t]  = gy * W + gx;
        sclsid[t] = (unsigned char)tcls[b * TT + t];
    }
    __syncthreads();

    float cls_sum = 0.0f, iou_sum = 0.0f, inner_sum = 0.0f;
    bool winner_flag = false;

    if (t < TT) {
        const int mycell = scell[t];

        // speculative gather — the 10 scattered loads overlap the scan below
        const int gy0 = mycell / W;
        const int gx0 = mycell - gy0 * W;
        const size_t HW  = (size_t)W * (size_t)W;
        const size_t off = (size_t)(b * 11) * HW + (size_t)gy0 * W + gx0;
        float cpred[NCLS];
        #pragma unroll
        for (int c = 0; c < NCLS; c++) cpred[c] = pred[off + (size_t)c * HW];
        const float px = pred[off + (size_t)7  * HW];
        const float py = pred[off + (size_t)8  * HW];
        const float pw = pred[off + (size_t)9  * HW];
        const float ph = pred[off + (size_t)10 * HW];

        // collision scan: last (highest index) target wins; OR class bits
        unsigned mask = 0u;
        bool winner = true;
        #pragma unroll
        for (int j = 0; j < TT; j++) {
            if (scell[j] == mycell) {
                mask |= 1u << sclsid[j];
                if (j > t) winner = false;
            }
        }

        if (winner) {
            #pragma unroll
            for (int c = 0; c < NCLS; c++) {
                const float tv = ((mask >> c) & 1u) ? 1.0f : 0.0f;
                cls_sum += bce_f(cpred[c], tv);
            }
            const float iou   = iou_f(px, py, pw, ph, txv, tyv, twv, thv);
            const float inner = iou_f(px, py, pw * 0.7f, ph * 0.7f,
                                      txv, tyv, twv * 0.7f, thv * 0.7f);
            iou_sum   = 1.0f - iou;
            inner_sum = 1.0f - inner;
            winner_flag = true;
        }
    }

    // block reduce over 64 threads (2 warps) — npos via ballot/popc (no shuffle chain)
    const unsigned fullm = 0xFFFFFFFFu;
    const int wincount = __popc(__ballot_sync(fullm, winner_flag));
    #pragma unroll
    for (int s = 16; s > 0; s >>= 1) {
        cls_sum   += __shfl_down_sync(fullm, cls_sum,   s);
        iou_sum   += __shfl_down_sync(fullm, iou_sum,   s);
        inner_sum += __shfl_down_sync(fullm, inner_sum, s);
    }
    __shared__ float red[2][4];
    __shared__ bool s_is_last;
    const int wid = t >> 5, lid = t & 31;
    if (lid == 0) {
        red[wid][0] = cls_sum; red[wid][1] = iou_sum;
        red[wid][2] = inner_sum; red[wid][3] = (float)wincount;
    }
    __syncthreads();

    // t0 publishes one STG.128 to its own slot, then acq_rel arrival (no membar)
    if (t == 0) {
        g_part[bx] = make_float4(red[0][0] + red[1][0],
                                 red[0][1] + red[1][1],
                                 red[0][2] + red[1][2],
                                 red[0][3] + red[1][3]);
        const unsigned prev = arrive_acq_rel(&g_count);   // release g_part[bx]
        s_is_last = (prev == NBLK - 1u);
    }
    __syncthreads();

    if (!s_is_last) return;

    // ── last block (acquire done via the acq_rel atomic): fixed-order tail ──
    __shared__ float sums[12];
    if (t < 12) {
        const int s = t >> 2, k = t & 3;
        float a0 = 0.0f, a1 = 0.0f, a2 = 0.0f, a3 = 0.0f;
        const float* gp = (const float*)&g_part[s * 64];
        #pragma unroll
        for (int i = 0; i < 16; i++) {
            a0 += __ldcg(gp + (i * 4 + 0) * 4 + k);
            a1 += __ldcg(gp + (i * 4 + 1) * 4 + k);
            a2 += __ldcg(gp + (i * 4 + 2) * 4 + k);
            a3 += __ldcg(gp + (i * 4 + 3) * 4 + k);
        }
        sums[t] = (a0 + a1) + (a2 + a3);
    }
    __syncthreads();

    if (t == 0) {
        float cls_total = 0.0f, box_total = 0.0f;
        #pragma unroll
        for (int s2 = 0; s2 < 3; s2++) {
            const float np        = sums[s2 * 4 + 3];
            const float denom     = np + 1e-8f;
            const float cls_loss  = sums[s2 * 4 + 0] / denom;
            const float iou_term  = sums[s2 * 4 + 1] / denom;
            const float inner_t   = sums[s2 * 4 + 2] / denom;
            const float inner_iou = 0.5f * iou_term + 0.5f * inner_t;  // (1-INNER_W), INNER_W
            const float box_loss  = 0.5f * iou_term + 0.5f * inner_iou;
            cls_total += cls_loss;
            box_total += box_loss;
        }
        cls_total = cls_total / 3.0f;
        box_total = box_total / 3.0f;
        const float total = 0.5f * cls_total + 7.5f * box_total;
        out[0] = total;
        out[1] = cls_total;
        out[2] = box_total;
        g_count = 0;   // reset for next graph replay (visible at kernel end)
    }
}

extern "C" void kernel_launch(void* const* d_in, const int* in_sizes, int n_in,
                              void* d_out, int out_size) {
    const float* p3   = (const float*)d_in[0];
    const float* p4   = (const float*)d_in[1];
    const float* p5   = (const float*)d_in[2];
    const int*   tcls = (const int*)  d_in[3];
    const float* tbox = (const float*)d_in[4];
    float* out = (float*)d_out;

    det_loss_fused<<<NBLK, 64>>>(p3, p4, p5, tcls, tbox, out);
}

// round 12
// speedup vs baseline: 1.2198x; 1.0372x over previous
#include <cuda_runtime.h>
#include <math.h>

#define NCLS 6
#define TT 60
#define NBLK 192   // 3 scales * 64 batches

// per-block partials: [cls_sum, iou_sum, inner_sum, npos] — fully rewritten every call
__device__ float g_part[NBLK * 4];
__device__ unsigned int g_count = 0;   // arrival counter; last block resets to 0

__device__ __forceinline__ float bce_f(float x, float t) {
    return fmaxf(x, 0.0f) - x * t + log1pf(expf(-fabsf(x)));
}

__device__ __forceinline__ float iou_f(float px, float py, float pw, float ph,
                                       float tx, float ty, float tw, float th) {
    float x11 = px - pw * 0.5f, y11 = py - ph * 0.5f;
    float x12 = px + pw * 0.5f, y12 = py + ph * 0.5f;
    float x21 = tx - tw * 0.5f, y21 = ty - th * 0.5f;
    float x22 = tx + tw * 0.5f, y22 = ty + th * 0.5f;
    float iw = fmaxf(fminf(x12, x22) - fmaxf(x11, x21), 0.0f);
    float ih = fmaxf(fminf(y12, y22) - fmaxf(y11, y21), 0.0f);
    float inter = iw * ih;
    float a1 = (x12 - x11) * (y12 - y11);
    float a2 = (x22 - x21) * (y22 - y21);
    return inter / (a1 + a2 - inter + 1e-7f);
}

__global__ void __launch_bounds__(64)
det_loss_fused(const float* __restrict__ p3,
               const float* __restrict__ p4,
               const float* __restrict__ p5,
               const int*   __restrict__ tcls,
               const float* __restrict__ tbox,
               float* __restrict__ out) {
    const int bx = blockIdx.x;
    const int scale = bx >> 6;        // 0,1,2
    const int b = bx & 63;
    const int W = 160 >> scale;       // H == W
    const float* __restrict__ pred = (scale == 0) ? p3 : ((scale == 1) ? p4 : p5);

    __shared__ int scell[TT];
    __shared__ unsigned char sclsid[TT];

    const int t = threadIdx.x;

    // Load this thread's target box early (coalesced float4)
    float txv = 0.f, tyv = 0.f, twv = 0.f, thv = 0.f;
    if (t < TT) {
        const float4 tb = ((const float4*)tbox)[(size_t)b * TT + t];
        txv = tb.x; tyv = tb.y; twv = tb.z; thv = tb.w;
        int gx = (int)(txv * (float)W);  gx = min(max(gx, 0), W - 1);
        int gy = (int)(tyv * (float)W);  gy = min(max(gy, 0), W - 1);
        scell[t]  = gy * W + gx;
        sclsid[t] = (unsigned char)tcls[b * TT + t];
    }
    __syncthreads();

    float cls_sum = 0.0f, iou_sum = 0.0f, inner_sum = 0.0f, npos = 0.0f;

    if (t < TT) {
        const int mycell = scell[t];

        // ── speculative gather: start the 10 scattered DRAM loads NOW so their
        //    latency overlaps the collision scan below ──
        const int gy0 = mycell / W;
        const int gx0 = mycell - gy0 * W;
        const size_t HW  = (size_t)W * (size_t)W;
        const size_t off = (size_t)(b * 11) * HW + (size_t)gy0 * W + gx0;
        float cpred[NCLS];
        #pragma unroll
        for (int c = 0; c < NCLS; c++) cpred[c] = pred[off + (size_t)c * HW];
        const float px = pred[off + (size_t)7  * HW];
        const float py = pred[off + (size_t)8  * HW];
        const float pw = pred[off + (size_t)9  * HW];
        const float ph = pred[off + (size_t)10 * HW];

        // ── collision scan (smem): last (highest t) target wins the cell;
        //    cls target is OR of class bits over co-located targets ──
        unsigned mask = 0u;
        bool winner = true;
        #pragma unroll
        for (int j = 0; j < TT; j++) {
            if (scell[j] == mycell) {
                mask |= 1u << sclsid[j];
                if (j > t) winner = false;
            }
        }

        if (winner) {
            #pragma unroll
            for (int c = 0; c < NCLS; c++) {
                const float tv = ((mask >> c) & 1u) ? 1.0f : 0.0f;
                cls_sum += bce_f(cpred[c], tv);
            }
            const float iou   = iou_f(px, py, pw, ph, txv, tyv, twv, thv);
            const float inner = iou_f(px, py, pw * 0.7f, ph * 0.7f,
                                      txv, tyv, twv * 0.7f, thv * 0.7f);
            iou_sum   = 1.0f - iou;
            inner_sum = 1.0f - inner;
            npos      = 1.0f;
        }
    }

    // block reduce over 64 threads (2 warps) — all lanes participate
    const unsigned fullm = 0xFFFFFFFFu;
    #pragma unroll
    for (int s = 16; s > 0; s >>= 1) {
        cls_sum   += __shfl_down_sync(fullm, cls_sum,   s);
        iou_sum   += __shfl_down_sync(fullm, iou_sum,   s);
        inner_sum += __shfl_down_sync(fullm, inner_sum, s);
        npos      += __shfl_down_sync(fullm, npos,      s);
    }
    __shared__ float red[2][4];
    __shared__ bool s_is_last;
    const int wid = t >> 5, lid = t & 31;
    if (lid == 0) {
        red[wid][0] = cls_sum; red[wid][1] = iou_sum;
        red[wid][2] = inner_sum; red[wid][3] = npos;
    }
    __syncthreads();
    if (t == 0) {
        g_part[bx * 4 + 0] = red[0][0] + red[1][0];
        g_part[bx * 4 + 1] = red[0][1] + red[1][1];
        g_part[bx * 4 + 2] = red[0][2] + red[1][2];
        g_part[bx * 4 + 3] = red[0][3] + red[1][3];
        __threadfence();                       // publish partials before arrival
        const unsigned prev = atomicAdd(&g_count, 1u);
        s_is_last = (prev == NBLK - 1u);
    }
    __syncthreads();

    if (!s_is_last) return;

    // ── last block: acquire, then PLAIN (batchable) loads; fixed-order sum ──
    __threadfence();                           // acquire: partials now visible
    __shared__ float sums[12];
    if (t < 12) {
        const int s = t >> 2, k = t & 3;
        float a0 = 0.0f, a1 = 0.0f, a2 = 0.0f, a3 = 0.0f;
        const int base = (s * 64) * 4 + k;
        #pragma unroll
        for (int i = 0; i < 16; i++) {
            a0 += g_part[base + (i * 4 + 0) * 4];
            a1 += g_part[base + (i * 4 + 1) * 4];
            a2 += g_part[base + (i * 4 + 2) * 4];
            a3 += g_part[base + (i * 4 + 3) * 4];
        }
        sums[t] = (a0 + a1) + (a2 + a3);
    }
    __syncthreads();

    if (t == 0) {
        float cls_total = 0.0f, box_total = 0.0f;
        #pragma unroll
        for (int s2 = 0; s2 < 3; s2++) {
            const float np        = sums[s2 * 4 + 3];
            const float denom     = np + 1e-8f;
            const float cls_loss  = sums[s2 * 4 + 0] / denom;
            const float iou_term  = sums[s2 * 4 + 1] / denom;
            const float inner_t   = sums[s2 * 4 + 2] / denom;
            const float inner_iou = 0.5f * iou_term + 0.5f * inner_t;  // (1-INNER_W), INNER_W
            const float box_loss  = 0.5f * iou_term + 0.5f * inner_iou;
            cls_total += cls_loss;
            box_total += box_loss;
        }
        cls_total = cls_total / 3.0f;
        box_total = box_total / 3.0f;
        const float total = 0.5f * cls_total + 7.5f * box_total;
        out[0] = total;
        out[1] = cls_total;
        out[2] = box_total;
        g_count = 0;   // reset for next (graph-replayed) launch
    }
}

extern "C" void kernel_launch(void* const* d_in, const int* in_sizes, int n_in,
                              void* d_out, int out_size) {
    const float* p3   = (const float*)d_in[0];
    const float* p4   = (const float*)d_in[1];
    const float* p5   = (const float*)d_in[2];
    const int*   tcls = (const int*)  d_in[3];
    const float* tbox = (const float*)d_in[4];
    float* out = (float*)d_out;

    det_loss_fused<<<NBLK, 64>>>(p3, p4, p5, tcls, tbox, out);
}